// round 1
// baseline (speedup 1.0000x reference)
#include <cuda_runtime.h>
#include <math.h>

#define N 2048
#define K 128
#define TJ 64          // j-tile rows held in shared memory
#define WPB 4          // warps per block in main kernel

__device__ float g_xs[N * K];   // standardized x, row-major [i][k]
__device__ float g_v[N];        // per-i: log S_joint - sum_k log S_marg

// ---------------------------------------------------------------------------
// Kernel A: per-column mean/std (ddof=1), standardize: xs = (x-mean)/(std+eps)
// One block per column k, 256 threads, 8 rows each.
// ---------------------------------------------------------------------------
__global__ __launch_bounds__(256) void stats_kernel(const float* __restrict__ z) {
    const int k = blockIdx.x;
    const int t = threadIdx.x;

    float vals[8];
    float s = 0.f, sq = 0.f;
#pragma unroll
    for (int r = 0; r < 8; r++) {
        float v = z[(t + 256 * r) * K + k];
        vals[r] = v;
        s += v;
        sq += v * v;
    }

    __shared__ float sh1[256];
    __shared__ float sh2[256];
    sh1[t] = s;
    sh2[t] = sq;
    __syncthreads();
    for (int off = 128; off > 0; off >>= 1) {
        if (t < off) {
            sh1[t] += sh1[t + off];
            sh2[t] += sh2[t + off];
        }
        __syncthreads();
    }

    __shared__ float s_mean, s_rstd;
    if (t == 0) {
        float sum = sh1[0], sumsq = sh2[0];
        float mean = sum / (float)N;
        float var = (sumsq - sum * mean) / (float)(N - 1);
        var = fmaxf(var, 0.f);
        float stdv = sqrtf(var);
        s_mean = mean;
        s_rstd = 1.f / (stdv + 1e-6f);
    }
    __syncthreads();

    const float mean = s_mean, rstd = s_rstd;
#pragma unroll
    for (int r = 0; r < 8; r++) {
        g_xs[(t + 256 * r) * K + k] = (vals[r] - mean) * rstd;
    }
}

// ---------------------------------------------------------------------------
// Kernel B: main O(N^2 K) pass. One warp per row i. Lane L owns dims
// k = 4L..4L+3 (one float4). For each j: e_k = exp2(C*d_k^2) accumulates the
// marginal sums; the joint term is the cross-lane PRODUCT of the e_k values
// (exp(-||xi-xj||^2/2) = prod_k e_k) -> no extra MUFU for the joint.
// ---------------------------------------------------------------------------
__device__ __forceinline__ void pair_body(const float4 xi, const float4 xj,
                                          float& sm0, float& sm1,
                                          float& sm2, float& sm3,
                                          float& sj) {
    const float Cc = -0.7213475204444817f;  // -0.5 * log2(e)
    float d0 = xi.x - xj.x;
    float d1 = xi.y - xj.y;
    float d2 = xi.z - xj.z;
    float d3 = xi.w - xj.w;
    float t0 = (d0 * Cc) * d0;
    float t1 = (d1 * Cc) * d1;
    float t2 = (d2 * Cc) * d2;
    float t3 = (d3 * Cc) * d3;
    float e0, e1, e2, e3;
    asm("ex2.approx.f32 %0, %1;" : "=f"(e0) : "f"(t0));
    asm("ex2.approx.f32 %0, %1;" : "=f"(e1) : "f"(t1));
    asm("ex2.approx.f32 %0, %1;" : "=f"(e2) : "f"(t2));
    asm("ex2.approx.f32 %0, %1;" : "=f"(e3) : "f"(t3));
    sm0 += e0;
    sm1 += e1;
    sm2 += e2;
    sm3 += e3;
    float p = (e0 * e1) * (e2 * e3);
#pragma unroll
    for (int o = 1; o < 32; o <<= 1)
        p *= __shfl_xor_sync(0xffffffffu, p, o);
    sj += p;  // identical value in all lanes
}

__global__ __launch_bounds__(WPB * 32) void main_kernel() {
    __shared__ float4 tile[TJ * 32];  // TJ rows x 128 floats = 32 KB

    const int warp = threadIdx.x >> 5;
    const int lane = threadIdx.x & 31;
    const int i = blockIdx.x * WPB + warp;

    const float4* xs4 = reinterpret_cast<const float4*>(g_xs);
    const float4 xi = xs4[i * 32 + lane];

    // two accumulator sets (halves fp32 summation error, adds ILP)
    float a0 = 0.f, a1 = 0.f, a2 = 0.f, a3 = 0.f, aj = 0.f;
    float b0 = 0.f, b1 = 0.f, b2 = 0.f, b3 = 0.f, bj = 0.f;

    for (int jt = 0; jt < N; jt += TJ) {
        __syncthreads();
#pragma unroll
        for (int r = 0; r < (TJ * 32) / (WPB * 32); r++) {
            int idx = threadIdx.x + (WPB * 32) * r;
            tile[idx] = xs4[jt * 32 + idx];
        }
        __syncthreads();

#pragma unroll 2
        for (int j = 0; j < TJ; j += 4) {
            pair_body(xi, tile[(j + 0) * 32 + lane], a0, a1, a2, a3, aj);
            pair_body(xi, tile[(j + 1) * 32 + lane], b0, b1, b2, b3, bj);
            pair_body(xi, tile[(j + 2) * 32 + lane], a0, a1, a2, a3, aj);
            pair_body(xi, tile[(j + 3) * 32 + lane], b0, b1, b2, b3, bj);
        }
    }

    // per-lane: sum of log of the 4 marginal sums this lane owns
    float lg = logf(a0 + b0) + logf(a1 + b1) + logf(a2 + b2) + logf(a3 + b3);
#pragma unroll
    for (int o = 16; o > 0; o >>= 1)
        lg += __shfl_xor_sync(0xffffffffu, lg, o);

    if (lane == 0) {
        float sj = aj + bj;       // identical across lanes
        g_v[i] = logf(sj) - lg;   // log S_joint - sum_k log S_marg
    }
}

// ---------------------------------------------------------------------------
// Kernel C: mean over i, add (K-1)*log(N), write scalar output.
// ---------------------------------------------------------------------------
__global__ __launch_bounds__(256) void finish_kernel(float* __restrict__ out) {
    __shared__ float sh[256];
    const int t = threadIdx.x;
    float s = 0.f;
    for (int r = t; r < N; r += 256) s += g_v[r];
    sh[t] = s;
    __syncthreads();
    for (int off = 128; off > 0; off >>= 1) {
        if (t < off) sh[t] += sh[t + off];
        __syncthreads();
    }
    if (t == 0) {
        float mean = sh[0] / (float)N;
        // LOSS_BETA = 1
        out[0] = mean + (float)(K - 1) * logf((float)N);
    }
}

// ---------------------------------------------------------------------------
extern "C" void kernel_launch(void* const* d_in, const int* in_sizes, int n_in,
                              void* d_out, int out_size) {
    (void)in_sizes; (void)n_in; (void)out_size;
    const float* z = (const float*)d_in[0];
    float* out = (float*)d_out;

    stats_kernel<<<K, 256>>>(z);
    main_kernel<<<N / WPB, WPB * 32>>>();
    finish_kernel<<<1, 256>>>(out);
}

// round 2
// speedup vs baseline: 1.0881x; 1.0881x over previous
#include <cuda_runtime.h>
#include <math.h>

#define N    2048
#define K    128
#define WPB  4            // warps (i-rows) per block
#define NT   (N / 32)     // 64 j-tiles of 32 rows
#define ROWF 132          // padded tile row stride (floats): 528B -> conflict-free LDS.128

// sqrt(log2(e)) : u = xs * SQL2E puts everything in base-2 exponent domain
#define SQL2E 1.2011224087864498f
#define LN2   0.6931471805599453f

__device__ float g_u[N * K];   // scaled standardized data, row-major
__device__ float g_v[N];       // per-i: log S_joint - sum_k log S_marg

// ---------------------------------------------------------------------------
// Kernel A: per-column mean/std (ddof=1); write u = (x-mean)/(std+eps)*SQL2E
// ---------------------------------------------------------------------------
__global__ __launch_bounds__(256) void stats_kernel(const float* __restrict__ z) {
    const int k = blockIdx.x;
    const int t = threadIdx.x;

    float vals[8];
    float s = 0.f, sq = 0.f;
#pragma unroll
    for (int r = 0; r < 8; r++) {
        float v = z[(t + 256 * r) * K + k];
        vals[r] = v;
        s += v;
        sq += v * v;
    }

    __shared__ float sh1[256], sh2[256];
    sh1[t] = s; sh2[t] = sq;
    __syncthreads();
    for (int off = 128; off > 0; off >>= 1) {
        if (t < off) { sh1[t] += sh1[t + off]; sh2[t] += sh2[t + off]; }
        __syncthreads();
    }

    __shared__ float s_mean, s_rs;
    if (t == 0) {
        float sum = sh1[0], sumsq = sh2[0];
        float mean = sum / (float)N;
        float var = (sumsq - sum * mean) / (float)(N - 1);
        var = fmaxf(var, 0.f);
        s_mean = mean;
        s_rs = SQL2E / (sqrtf(var) + 1e-6f);
    }
    __syncthreads();

    const float mean = s_mean, rs = s_rs;
#pragma unroll
    for (int r = 0; r < 8; r++)
        g_u[(t + 256 * r) * K + k] = (vals[r] - mean) * rs;
}

// ---------------------------------------------------------------------------
// cp.async helpers: copy one 32x128-float tile (16KB) into padded smem rows
// ---------------------------------------------------------------------------
__device__ __forceinline__ void tile_copy(float* dst_base, const float* src_base, int tid) {
#pragma unroll
    for (int r = 0; r < 8; r++) {
        int e = (tid + 128 * r) * 4;          // float index in 32x128 tile
        int row = e >> 7, col = e & 127;
        unsigned d = (unsigned)__cvta_generic_to_shared(dst_base + row * ROWF + col);
        asm volatile("cp.async.cg.shared.global [%0], [%1], 16;" :: "r"(d), "l"(src_base + e));
    }
}

// ---------------------------------------------------------------------------
// Kernel B: main O(N^2 K) pass.
// Warp = one i-row. Lane = one j per tile; iterates all 128 k.
// marg term exponent: t_k = u_j * (u_i - u_j/2)  (hi_k factored out)
// joint exponent    : Hi + sum_k t_k             (reuses t_k, plain FADD)
// 128 per-lane register accumulators; one butterfly pass at the end.
// ---------------------------------------------------------------------------
__global__ __launch_bounds__(128) void main_kernel() {
    __shared__ float uj[2][32 * ROWF];    // double-buffered j-tile
    __shared__ float ui_s[WPB][ROWF];     // block's 4 i-rows

    const int tid = threadIdx.x;
    const int warp = tid >> 5, lane = tid & 31;
    const int i = blockIdx.x * WPB + warp;

    // load block's i-rows into smem (512 floats)
#pragma unroll
    for (int r = 0; r < 4; r++) {
        int e = tid + 128 * r;
        ui_s[e >> 7][e & 127] = g_u[(blockIdx.x * WPB + (e >> 7)) * K + (e & 127)];
    }

    // prefetch tile 0
    tile_copy(uj[0], g_u, tid);
    asm volatile("cp.async.commit_group;");

    __syncthreads();

    // Hi = -||u_i||^2 / 2 (base-2 exponent domain)
    float4 mu = *(const float4*)(&ui_s[warp][lane * 4]);
    float hh = mu.x * mu.x + mu.y * mu.y + mu.z * mu.z + mu.w * mu.w;
#pragma unroll
    for (int o = 16; o; o >>= 1) hh += __shfl_xor_sync(0xffffffffu, hh, o);
    const float Hi = -0.5f * hh;

    float m[128];
#pragma unroll
    for (int k = 0; k < 128; k++) m[k] = 0.f;
    float J = 0.f;

    const float* U = ui_s[warp];

#pragma unroll 1
    for (int t = 0; t < NT; t++) {
        if (t + 1 < NT) {
            tile_copy(uj[(t + 1) & 1], g_u + (t + 1) * 32 * K, tid);
            asm volatile("cp.async.commit_group;");
            asm volatile("cp.async.wait_group 1;");
        } else {
            asm volatile("cp.async.wait_group 0;");
        }
        __syncthreads();

        const float* R = &uj[t & 1][lane * ROWF];
        float s0 = 0.f, s1 = 0.f, s2 = 0.f, s3 = 0.f;
#pragma unroll
        for (int c = 0; c < 32; c++) {
            float4 a = *(const float4*)(U + c * 4);   // broadcast
            float4 b = *(const float4*)(R + c * 4);   // conflict-free
            float t0 = b.x * fmaf(-0.5f, b.x, a.x);
            float t1 = b.y * fmaf(-0.5f, b.y, a.y);
            float t2 = b.z * fmaf(-0.5f, b.z, a.z);
            float t3 = b.w * fmaf(-0.5f, b.w, a.w);
            float e0, e1, e2, e3;
            asm("ex2.approx.f32 %0, %1;" : "=f"(e0) : "f"(t0));
            asm("ex2.approx.f32 %0, %1;" : "=f"(e1) : "f"(t1));
            asm("ex2.approx.f32 %0, %1;" : "=f"(e2) : "f"(t2));
            asm("ex2.approx.f32 %0, %1;" : "=f"(e3) : "f"(t3));
            m[c * 4 + 0] += e0;
            m[c * 4 + 1] += e1;
            m[c * 4 + 2] += e2;
            m[c * 4 + 3] += e3;
            s0 += t0; s1 += t1; s2 += t2; s3 += t3;
        }
        float sj = ((s0 + s1) + (s2 + s3)) + Hi;
        float ej;
        asm("ex2.approx.f32 %0, %1;" : "=f"(ej) : "f"(sj));
        J += ej;
        __syncthreads();
    }

    // epilogue: reduce marginal sums across lanes, take logs
    float LG = 0.f;
#pragma unroll
    for (int k = 0; k < 128; k++) {
        float v = m[k];
#pragma unroll
        for (int o = 16; o; o >>= 1) v += __shfl_xor_sync(0xffffffffu, v, o);
        LG += logf(v);
    }
#pragma unroll
    for (int o = 16; o; o >>= 1) J += __shfl_xor_sync(0xffffffffu, J, o);

    if (lane == 0)
        g_v[i] = logf(J) - LN2 * Hi - LG;   // ln S_joint - sum_k ln S_marg
}

// ---------------------------------------------------------------------------
// Kernel C: mean over i + (K-1)*ln(N)
// ---------------------------------------------------------------------------
__global__ __launch_bounds__(256) void finish_kernel(float* __restrict__ out) {
    __shared__ float sh[256];
    const int t = threadIdx.x;
    float s = 0.f;
    for (int r = t; r < N; r += 256) s += g_v[r];
    sh[t] = s;
    __syncthreads();
    for (int off = 128; off > 0; off >>= 1) {
        if (t < off) sh[t] += sh[t + off];
        __syncthreads();
    }
    if (t == 0)
        out[0] = sh[0] / (float)N + (float)(K - 1) * logf((float)N);
}

// ---------------------------------------------------------------------------
extern "C" void kernel_launch(void* const* d_in, const int* in_sizes, int n_in,
                              void* d_out, int out_size) {
    (void)in_sizes; (void)n_in; (void)out_size;
    const float* z = (const float*)d_in[0];
    float* out = (float*)d_out;

    stats_kernel<<<K, 256>>>(z);
    main_kernel<<<N / WPB, WPB * 32>>>();
    finish_kernel<<<1, 256>>>(out);
}

// round 3
// speedup vs baseline: 1.4017x; 1.2883x over previous
#include <cuda_runtime.h>
#include <math.h>

#define N    2048
#define K    128
#define NMAX 64              // moment-expansion order

#define SQL2E 1.2011224087864498f   // sqrt(log2(e))
#define NL2E  -0.7213475204444817f  // -0.5*log2(e)

__device__ float  g_u [N * K];      // standardized * sqrt(log2 e)  (base-2 domain)
__device__ float  g_xs[N * K];      // standardized (natural domain)
__device__ float  g_rh[N];          // 0.5*||u_i||^2
__device__ float  g_S [N];          // joint sums  S_i = sum_j exp(-sq_ij/2)
__device__ double g_T [NMAX * K];   // T'[n][k] = (1/n!) sum_j e^{-b^2/2} b^n
__device__ float  g_v [N];

__device__ __forceinline__ float ex2f(float x) {
    float r; asm("ex2.approx.f32 %0, %1;" : "=f"(r) : "f"(x)); return r;
}

// ---------------------------------------------------------------------------
// A: per-column mean/std (ddof=1); writes xs and u; zeroes g_S.
// ---------------------------------------------------------------------------
__global__ __launch_bounds__(256) void stats_kernel(const float* __restrict__ z) {
    const int k = blockIdx.x;
    const int t = threadIdx.x;

    int gt = blockIdx.x * 256 + t;
    if (gt < N) g_S[gt] = 0.f;

    float vals[8];
    float s = 0.f, sq = 0.f;
#pragma unroll
    for (int r = 0; r < 8; r++) {
        float v = z[(t + 256 * r) * K + k];
        vals[r] = v; s += v; sq += v * v;
    }

    __shared__ float sh1[256], sh2[256];
    sh1[t] = s; sh2[t] = sq;
    __syncthreads();
    for (int off = 128; off > 0; off >>= 1) {
        if (t < off) { sh1[t] += sh1[t + off]; sh2[t] += sh2[t + off]; }
        __syncthreads();
    }
    __shared__ float s_mean, s_r;
    if (t == 0) {
        float sum = sh1[0], sumsq = sh2[0];
        float mean = sum / (float)N;
        float var = (sumsq - sum * mean) / (float)(N - 1);
        var = fmaxf(var, 0.f);
        s_mean = mean;
        s_r = 1.f / (sqrtf(var) + 1e-6f);
    }
    __syncthreads();
    const float mean = s_mean, rs = s_r;
#pragma unroll
    for (int r = 0; r < 8; r++) {
        float xsv = (vals[r] - mean) * rs;
        g_xs[(t + 256 * r) * K + k] = xsv;
        g_u [(t + 256 * r) * K + k] = xsv * SQL2E;
    }
}

// ---------------------------------------------------------------------------
// R: per-row 0.5*||u_i||^2.  One warp per row.
// ---------------------------------------------------------------------------
__global__ __launch_bounds__(256) void rownorm_kernel() {
    const int warp = threadIdx.x >> 5, lane = threadIdx.x & 31;
    const int i = blockIdx.x * 8 + warp;
    const float4 v = reinterpret_cast<const float4*>(g_u)[i * 32 + lane];
    float h = v.x * v.x + v.y * v.y + v.z * v.z + v.w * v.w;
#pragma unroll
    for (int o = 16; o; o >>= 1) h += __shfl_xor_sync(0xffffffffu, h, o);
    if (lane == 0) g_rh[i] = 0.5f * h;
}

// ---------------------------------------------------------------------------
// M: moments. Block per column k. T'[n][k] = (1/n!) sum_j w_j b_j^n, fp64.
// ---------------------------------------------------------------------------
__global__ __launch_bounds__(256) void moment_kernel() {
    const int k = blockIdx.x;
    const int tid = threadIdx.x;
    const int lane = tid & 31;

    __shared__ double T_sh[NMAX];
    if (tid < NMAX) T_sh[tid] = 0.0;
    __syncthreads();

    double b[8], p[8];
#pragma unroll
    for (int r = 0; r < 8; r++) {
        float bx = g_xs[(tid * 8 + r) * K + k];
        b[r] = (double)bx;
        p[r] = (double)ex2f(NL2E * bx * bx);   // w = e^{-b^2/2}
    }

#pragma unroll 1
    for (int oct = 0; oct < 8; oct++) {
        double acc[8];
#pragma unroll
        for (int m = 0; m < 8; m++) acc[m] = 0.0;
#pragma unroll
        for (int r = 0; r < 8; r++) {
            double q = p[r];
#pragma unroll
            for (int m = 0; m < 8; m++) { acc[m] += q; q *= b[r]; }
            p[r] = q;
        }
#pragma unroll
        for (int m = 0; m < 8; m++) {
#pragma unroll
            for (int o = 16; o; o >>= 1)
                acc[m] += __shfl_xor_sync(0xffffffffu, acc[m], o);
        }
        if (lane == 0) {
#pragma unroll
            for (int m = 0; m < 8; m++) atomicAdd(&T_sh[oct * 8 + m], acc[m]);
        }
    }
    __syncthreads();
    if (tid < NMAX) {
        double f = 1.0;
        for (int m = 2; m <= tid; m++) f *= (double)m;
        g_T[tid * K + k] = T_sh[tid] / f;
    }
}

// ---------------------------------------------------------------------------
// G: symmetric Gram + fused exp + row/col sums.  136 blocks (upper triangle
// of 16x16 tile grid), 128x128 output tile, 256 threads, 8x8 microtiles.
// ---------------------------------------------------------------------------
__global__ __launch_bounds__(256) void gram_kernel() {
    __shared__ float As[32][132];
    __shared__ float Bs[32][132];
    __shared__ float colP[16][128];

    const int tid = threadIdx.x;
    const int tx = tid & 15, ty = tid >> 4;

    // map linear block id -> (ti, tj) with ti <= tj
    int rem = blockIdx.x, ti = 0;
    for (int t = 0; t < 16; t++) {
        int L = 16 - t;
        if (rem < L) { ti = t; break; }
        rem -= L;
    }
    const int tj = ti + rem;
    const int i0 = ti * 128, j0 = tj * 128;

    float acc[8][8];
#pragma unroll
    for (int m = 0; m < 8; m++)
#pragma unroll
        for (int n = 0; n < 8; n++) acc[m][n] = 0.f;

#pragma unroll 1
    for (int kc = 0; kc < K; kc += 32) {
        __syncthreads();
#pragma unroll
        for (int r = 0; r < 4; r++) {
            int f = tid + 256 * r;
            int row = f >> 3, kp = (f & 7) * 4;
            float4 va = *(const float4*)&g_u[(i0 + row) * K + kc + kp];
            As[kp + 0][row] = va.x; As[kp + 1][row] = va.y;
            As[kp + 2][row] = va.z; As[kp + 3][row] = va.w;
            float4 vb = *(const float4*)&g_u[(j0 + row) * K + kc + kp];
            Bs[kp + 0][row] = vb.x; Bs[kp + 1][row] = vb.y;
            Bs[kp + 2][row] = vb.z; Bs[kp + 3][row] = vb.w;
        }
        __syncthreads();
#pragma unroll
        for (int kk = 0; kk < 32; kk++) {
            float4 a0 = *(const float4*)&As[kk][ty * 8];
            float4 a1 = *(const float4*)&As[kk][ty * 8 + 4];
            float4 b0 = *(const float4*)&Bs[kk][tx * 8];
            float4 b1 = *(const float4*)&Bs[kk][tx * 8 + 4];
            float av[8] = {a0.x, a0.y, a0.z, a0.w, a1.x, a1.y, a1.z, a1.w};
            float bv[8] = {b0.x, b0.y, b0.z, b0.w, b1.x, b1.y, b1.z, b1.w};
#pragma unroll
            for (int m = 0; m < 8; m++)
#pragma unroll
                for (int n = 0; n < 8; n++) acc[m][n] += av[m] * bv[n];
        }
    }

    // epilogue: e = 2^(G - rh_i - rh_j); accumulate row & col sums
    float rhi[8], rhj[8];
#pragma unroll
    for (int m = 0; m < 8; m++) rhi[m] = g_rh[i0 + ty * 8 + m];
#pragma unroll
    for (int n = 0; n < 8; n++) rhj[n] = g_rh[j0 + tx * 8 + n];

    float rows[8], cols[8];
#pragma unroll
    for (int m = 0; m < 8; m++) rows[m] = 0.f;
#pragma unroll
    for (int n = 0; n < 8; n++) cols[n] = 0.f;
#pragma unroll
    for (int m = 0; m < 8; m++) {
#pragma unroll
        for (int n = 0; n < 8; n++) {
            float e = ex2f(acc[m][n] - rhi[m] - rhj[n]);
            rows[m] += e;
            cols[n] += e;
        }
    }

    // row sums: reduce across tx (lanes xor 1,2,4,8 stay in 16-lane group)
#pragma unroll
    for (int o = 8; o; o >>= 1)
#pragma unroll
        for (int m = 0; m < 8; m++)
            rows[m] += __shfl_xor_sync(0xffffffffu, rows[m], o);
    if (tx == 0) {
#pragma unroll
        for (int m = 0; m < 8; m++)
            atomicAdd(&g_S[i0 + ty * 8 + m], rows[m]);
    }

    // col sums (only for off-diagonal tiles: tile also counts as (j,i))
#pragma unroll
    for (int n = 0; n < 8; n++) colP[ty][tx * 8 + n] = cols[n];
    __syncthreads();
    if (ti != tj && tid < 128) {
        float s = 0.f;
#pragma unroll
        for (int t = 0; t < 16; t++) s += colP[t][tid];
        atomicAdd(&g_S[j0 + tid], s);
    }
}

// ---------------------------------------------------------------------------
// C: combine. Block = 8 rows i, thread = column k. Horner in fp64:
//   P(a) = sum_n a^n T'[n][k];  ln m_ik = ln P - a^2/2
//   v_i  = ln S_i - sum_k ln m_ik
// ---------------------------------------------------------------------------
__global__ __launch_bounds__(128) void combine_kernel() {
    const int k = threadIdx.x;
    const int i0 = blockIdx.x * 8;

    float af[8];
    double a[8], S[8];
#pragma unroll
    for (int r = 0; r < 8; r++) {
        af[r] = g_xs[(i0 + r) * K + k];
        a[r] = (double)af[r];
    }
    {
        double t = g_T[(NMAX - 1) * K + k];
#pragma unroll
        for (int r = 0; r < 8; r++) S[r] = t;
    }
#pragma unroll 4
    for (int n = NMAX - 2; n >= 0; n--) {
        double t = g_T[n * K + k];
#pragma unroll
        for (int r = 0; r < 8; r++) S[r] = fma(S[r], a[r], t);
    }

    float val[8];
#pragma unroll
    for (int r = 0; r < 8; r++)
        val[r] = logf((float)S[r]) - 0.5f * af[r] * af[r];

#pragma unroll
    for (int o = 16; o; o >>= 1)
#pragma unroll
        for (int r = 0; r < 8; r++)
            val[r] += __shfl_xor_sync(0xffffffffu, val[r], o);

    __shared__ float part[4][8];
    const int w = k >> 5, lane = k & 31;
    if (lane == 0) {
#pragma unroll
        for (int r = 0; r < 8; r++) part[w][r] = val[r];
    }
    __syncthreads();
    if (k < 8) {
        float tot = part[0][k] + part[1][k] + part[2][k] + part[3][k];
        g_v[i0 + k] = logf(g_S[i0 + k]) - tot;
    }
}

// ---------------------------------------------------------------------------
// F: mean + (K-1)*ln N
// ---------------------------------------------------------------------------
__global__ __launch_bounds__(256) void finish_kernel(float* __restrict__ out) {
    __shared__ float sh[256];
    const int t = threadIdx.x;
    float s = 0.f;
    for (int r = t; r < N; r += 256) s += g_v[r];
    sh[t] = s;
    __syncthreads();
    for (int off = 128; off > 0; off >>= 1) {
        if (t < off) sh[t] += sh[t + off];
        __syncthreads();
    }
    if (t == 0)
        out[0] = sh[0] / (float)N + (float)(K - 1) * logf((float)N);
}

// ---------------------------------------------------------------------------
extern "C" void kernel_launch(void* const* d_in, const int* in_sizes, int n_in,
                              void* d_out, int out_size) {
    (void)in_sizes; (void)n_in; (void)out_size;
    const float* z = (const float*)d_in[0];
    float* out = (float*)d_out;

    stats_kernel  <<<K, 256>>>(z);
    rownorm_kernel<<<N / 8, 256>>>();
    moment_kernel <<<K, 256>>>();
    gram_kernel   <<<136, 256>>>();
    combine_kernel<<<N / 8, 128>>>();
    finish_kernel <<<1, 256>>>(out);
}

// round 4
// speedup vs baseline: 5.6471x; 4.0287x over previous
#include <cuda_runtime.h>
#include <math.h>

#define N    2048
#define K    128
#define NMAX 64

#define SQL2E 1.2011224087864498f   // sqrt(log2(e))
#define NL2E  -0.7213475204444817f  // -0.5*log2(e)

__device__ float g_u [N * K];     // standardized * sqrt(log2 e)  (base-2 domain)
__device__ float g_xs[N * K];     // standardized (natural domain)
__device__ float g_rh[N];         // 0.5*||u_i||^2
__device__ float g_S [N];         // joint sums  S_i = sum_j exp(-sq_ij/2)
__device__ float g_T [NMAX * K];  // T'[n][k] = (1/n!) sum_j e^{-b^2/2} b^n
__device__ float g_v [N];

__device__ const float c_rinv[NMAX] = {
    1.f/1,1.f/2,1.f/3,1.f/4,1.f/5,1.f/6,1.f/7,1.f/8,
    1.f/9,1.f/10,1.f/11,1.f/12,1.f/13,1.f/14,1.f/15,1.f/16,
    1.f/17,1.f/18,1.f/19,1.f/20,1.f/21,1.f/22,1.f/23,1.f/24,
    1.f/25,1.f/26,1.f/27,1.f/28,1.f/29,1.f/30,1.f/31,1.f/32,
    1.f/33,1.f/34,1.f/35,1.f/36,1.f/37,1.f/38,1.f/39,1.f/40,
    1.f/41,1.f/42,1.f/43,1.f/44,1.f/45,1.f/46,1.f/47,1.f/48,
    1.f/49,1.f/50,1.f/51,1.f/52,1.f/53,1.f/54,1.f/55,1.f/56,
    1.f/57,1.f/58,1.f/59,1.f/60,1.f/61,1.f/62,1.f/63,1.f/64 };

__device__ __forceinline__ float ex2f(float x) {
    float r; asm("ex2.approx.f32 %0, %1;" : "=f"(r) : "f"(x)); return r;
}

// ---------------------------------------------------------------------------
// A: per-column mean/std (ddof=1) + standardize + fp32 scaled moments.
// Block = one column k; thread holds rows {t+256r}.
// T'[n][k] = sum_j e^{-b^2/2} b^n / n!  via q_{n+1} = q_n * b * (1/(n+1)).
// ---------------------------------------------------------------------------
__global__ __launch_bounds__(256) void stats_kernel(const float* __restrict__ z) {
    const int k = blockIdx.x;
    const int t = threadIdx.x;
    const int lane = t & 31;

    int gt = blockIdx.x * 256 + t;
    if (gt < N) g_S[gt] = 0.f;

    float vals[8];
    float s = 0.f, sq = 0.f;
#pragma unroll
    for (int r = 0; r < 8; r++) {
        float v = z[(t + 256 * r) * K + k];
        vals[r] = v; s += v; sq += v * v;
    }

    __shared__ float sh1[256], sh2[256];
    sh1[t] = s; sh2[t] = sq;
    __syncthreads();
    for (int off = 128; off > 0; off >>= 1) {
        if (t < off) { sh1[t] += sh1[t + off]; sh2[t] += sh2[t + off]; }
        __syncthreads();
    }
    __shared__ float s_mean, s_r;
    if (t == 0) {
        float sum = sh1[0], sumsq = sh2[0];
        float mean = sum / (float)N;
        float var = (sumsq - sum * mean) / (float)(N - 1);
        var = fmaxf(var, 0.f);
        s_mean = mean;
        s_r = 1.f / (sqrtf(var) + 1e-6f);
    }
    __syncthreads();
    const float mean = s_mean, rs = s_r;

    float b[8], p[8];
#pragma unroll
    for (int r = 0; r < 8; r++) {
        float xsv = (vals[r] - mean) * rs;
        g_xs[(t + 256 * r) * K + k] = xsv;
        g_u [(t + 256 * r) * K + k] = xsv * SQL2E;
        b[r] = xsv;
        p[r] = ex2f(NL2E * xsv * xsv);   // w = e^{-b^2/2}
    }

    __shared__ float T_sh[NMAX];
    if (t < NMAX) T_sh[t] = 0.f;
    __syncthreads();

#pragma unroll 1
    for (int oct = 0; oct < 8; oct++) {
        float acc[8];
#pragma unroll
        for (int m = 0; m < 8; m++) acc[m] = 0.f;
#pragma unroll
        for (int r = 0; r < 8; r++) {
            float q = p[r];
#pragma unroll
            for (int m = 0; m < 8; m++) {
                acc[m] += q;
                q *= b[r] * c_rinv[oct * 8 + m];
            }
            p[r] = q;
        }
#pragma unroll
        for (int m = 0; m < 8; m++) {
#pragma unroll
            for (int o = 16; o; o >>= 1)
                acc[m] += __shfl_xor_sync(0xffffffffu, acc[m], o);
        }
        if (lane == 0) {
#pragma unroll
            for (int m = 0; m < 8; m++) atomicAdd(&T_sh[oct * 8 + m], acc[m]);
        }
    }
    __syncthreads();
    if (t < NMAX) g_T[t * K + k] = T_sh[t];
}

// ---------------------------------------------------------------------------
// R: per-row 0.5*||u_i||^2.
// ---------------------------------------------------------------------------
__global__ __launch_bounds__(256) void rownorm_kernel() {
    const int warp = threadIdx.x >> 5, lane = threadIdx.x & 31;
    const int i = blockIdx.x * 8 + warp;
    const float4 v = reinterpret_cast<const float4*>(g_u)[i * 32 + lane];
    float h = v.x * v.x + v.y * v.y + v.z * v.z + v.w * v.w;
#pragma unroll
    for (int o = 16; o; o >>= 1) h += __shfl_xor_sync(0xffffffffu, h, o);
    if (lane == 0) g_rh[i] = 0.5f * h;
}

// ---------------------------------------------------------------------------
// G: symmetric Gram + fused exp + row/col sums (fp32, unchanged).
// ---------------------------------------------------------------------------
__global__ __launch_bounds__(256) void gram_kernel() {
    __shared__ float As[32][132];
    __shared__ float Bs[32][132];
    __shared__ float colP[16][128];

    const int tid = threadIdx.x;
    const int tx = tid & 15, ty = tid >> 4;

    int rem = blockIdx.x, ti = 0;
    for (int t = 0; t < 16; t++) {
        int L = 16 - t;
        if (rem < L) { ti = t; break; }
        rem -= L;
    }
    const int tj = ti + rem;
    const int i0 = ti * 128, j0 = tj * 128;

    float acc[8][8];
#pragma unroll
    for (int m = 0; m < 8; m++)
#pragma unroll
        for (int n = 0; n < 8; n++) acc[m][n] = 0.f;

#pragma unroll 1
    for (int kc = 0; kc < K; kc += 32) {
        __syncthreads();
#pragma unroll
        for (int r = 0; r < 4; r++) {
            int f = tid + 256 * r;
            int row = f >> 3, kp = (f & 7) * 4;
            float4 va = *(const float4*)&g_u[(i0 + row) * K + kc + kp];
            As[kp + 0][row] = va.x; As[kp + 1][row] = va.y;
            As[kp + 2][row] = va.z; As[kp + 3][row] = va.w;
            float4 vb = *(const float4*)&g_u[(j0 + row) * K + kc + kp];
            Bs[kp + 0][row] = vb.x; Bs[kp + 1][row] = vb.y;
            Bs[kp + 2][row] = vb.z; Bs[kp + 3][row] = vb.w;
        }
        __syncthreads();
#pragma unroll
        for (int kk = 0; kk < 32; kk++) {
            float4 a0 = *(const float4*)&As[kk][ty * 8];
            float4 a1 = *(const float4*)&As[kk][ty * 8 + 4];
            float4 b0 = *(const float4*)&Bs[kk][tx * 8];
            float4 b1 = *(const float4*)&Bs[kk][tx * 8 + 4];
            float av[8] = {a0.x, a0.y, a0.z, a0.w, a1.x, a1.y, a1.z, a1.w};
            float bv[8] = {b0.x, b0.y, b0.z, b0.w, b1.x, b1.y, b1.z, b1.w};
#pragma unroll
            for (int m = 0; m < 8; m++)
#pragma unroll
                for (int n = 0; n < 8; n++) acc[m][n] += av[m] * bv[n];
        }
    }

    float rhi[8], rhj[8];
#pragma unroll
    for (int m = 0; m < 8; m++) rhi[m] = g_rh[i0 + ty * 8 + m];
#pragma unroll
    for (int n = 0; n < 8; n++) rhj[n] = g_rh[j0 + tx * 8 + n];

    float rows[8], cols[8];
#pragma unroll
    for (int m = 0; m < 8; m++) rows[m] = 0.f;
#pragma unroll
    for (int n = 0; n < 8; n++) cols[n] = 0.f;
#pragma unroll
    for (int m = 0; m < 8; m++) {
#pragma unroll
        for (int n = 0; n < 8; n++) {
            float e = ex2f(acc[m][n] - rhi[m] - rhj[n]);
            rows[m] += e;
            cols[n] += e;
        }
    }

#pragma unroll
    for (int o = 8; o; o >>= 1)
#pragma unroll
        for (int m = 0; m < 8; m++)
            rows[m] += __shfl_xor_sync(0xffffffffu, rows[m], o);
    if (tx == 0) {
#pragma unroll
        for (int m = 0; m < 8; m++)
            atomicAdd(&g_S[i0 + ty * 8 + m], rows[m]);
    }

#pragma unroll
    for (int n = 0; n < 8; n++) colP[ty][tx * 8 + n] = cols[n];
    __syncthreads();
    if (ti != tj && tid < 128) {
        float s = 0.f;
#pragma unroll
        for (int t = 0; t < 16; t++) s += colP[t][tid];
        atomicAdd(&g_S[j0 + tid], s);
    }
}

// ---------------------------------------------------------------------------
// C: combine, fp32 Horner. Block = 8 rows, thread = column k.
// ---------------------------------------------------------------------------
__global__ __launch_bounds__(128) void combine_kernel() {
    const int k = threadIdx.x;
    const int i0 = blockIdx.x * 8;

    float a[8], S[8];
#pragma unroll
    for (int r = 0; r < 8; r++) a[r] = g_xs[(i0 + r) * K + k];
    {
        float t = g_T[(NMAX - 1) * K + k];
#pragma unroll
        for (int r = 0; r < 8; r++) S[r] = t;
    }
#pragma unroll 8
    for (int n = NMAX - 2; n >= 0; n--) {
        float t = g_T[n * K + k];
#pragma unroll
        for (int r = 0; r < 8; r++) S[r] = fmaf(S[r], a[r], t);
    }

    float val[8];
#pragma unroll
    for (int r = 0; r < 8; r++)
        val[r] = logf(S[r]) - 0.5f * a[r] * a[r];

#pragma unroll
    for (int o = 16; o; o >>= 1)
#pragma unroll
        for (int r = 0; r < 8; r++)
            val[r] += __shfl_xor_sync(0xffffffffu, val[r], o);

    __shared__ float part[4][8];
    const int w = k >> 5, lane = k & 31;
    if (lane == 0) {
#pragma unroll
        for (int r = 0; r < 8; r++) part[w][r] = val[r];
    }
    __syncthreads();
    if (k < 8) {
        float tot = part[0][k] + part[1][k] + part[2][k] + part[3][k];
        g_v[i0 + k] = logf(g_S[i0 + k]) - tot;
    }
}

// ---------------------------------------------------------------------------
// F: mean + (K-1)*ln N
// ---------------------------------------------------------------------------
__global__ __launch_bounds__(256) void finish_kernel(float* __restrict__ out) {
    __shared__ float sh[256];
    const int t = threadIdx.x;
    float s = 0.f;
    for (int r = t; r < N; r += 256) s += g_v[r];
    sh[t] = s;
    __syncthreads();
    for (int off = 128; off > 0; off >>= 1) {
        if (t < off) sh[t] += sh[t + off];
        __syncthreads();
    }
    if (t == 0)
        out[0] = sh[0] / (float)N + (float)(K - 1) * logf((float)N);
}

// ---------------------------------------------------------------------------
extern "C" void kernel_launch(void* const* d_in, const int* in_sizes, int n_in,
                              void* d_out, int out_size) {
    (void)in_sizes; (void)n_in; (void)out_size;
    const float* z = (const float*)d_in[0];
    float* out = (float*)d_out;

    stats_kernel  <<<K, 256>>>(z);
    rownorm_kernel<<<N / 8, 256>>>();
    gram_kernel   <<<136, 256>>>();
    combine_kernel<<<N / 8, 128>>>();
    finish_kernel <<<1, 256>>>(out);
}

// round 5
// speedup vs baseline: 5.9463x; 1.0530x over previous
#include <cuda_runtime.h>
#include <math.h>

#define N    2048
#define K    128
#define NMAX 64

#define SQL2E 1.2011224087864498f   // sqrt(log2(e))
#define NL2E  -0.7213475204444817f  // -0.5*log2(e)

typedef unsigned long long ull;

__device__ float g_u  [N * K];      // standardized * sqrt(log2 e)
__device__ float g_xs [N * K];      // standardized
__device__ float g_rh [N];          // 0.5*||u_i||^2
__device__ float g_S  [N];          // joint sums
__device__ float g_T  [NMAX * K];   // scaled moments
__device__ float g_v  [N];
__device__ float g_pS [64 * K];     // partial column sums
__device__ float g_pQ [64 * K];     // partial column sumsq
__device__ float g_mean[K], g_rs[K];

__device__ __forceinline__ float ex2f(float x) {
    float r; asm("ex2.approx.f32 %0, %1;" : "=f"(r) : "f"(x)); return r;
}
__device__ __forceinline__ float lg2f(float x) {
    float r; asm("lg2.approx.f32 %0, %1;" : "=f"(r) : "f"(x)); return r;
}
#define LN2f 0.6931471805599453f
__device__ __forceinline__ float lnf(float x) { return lg2f(x) * LN2f; }

__device__ __forceinline__ ull splat2(float x) {
    ull r; asm("mov.b64 %0, {%1, %1};" : "=l"(r) : "f"(x)); return r;
}
__device__ __forceinline__ ull pack2(float lo, float hi) {
    ull r; asm("mov.b64 %0, {%1, %2};" : "=l"(r) : "f"(lo), "f"(hi)); return r;
}
__device__ __forceinline__ ull fma2(ull a, ull b, ull c) {
    ull d; asm("fma.rn.f32x2 %0, %1, %2, %3;" : "=l"(d) : "l"(a), "l"(b), "l"(c)); return d;
}
__device__ __forceinline__ void unpack2(ull v, float& lo, float& hi) {
    asm("mov.b64 {%0, %1}, %2;" : "=f"(lo), "=f"(hi) : "l"(v));
}

// ---------------------------------------------------------------------------
// S1: partial column sums. 64 blocks x 32 rows; thread = column k; coalesced.
// ---------------------------------------------------------------------------
__global__ __launch_bounds__(128) void sums_kernel(const float* __restrict__ z) {
    const int k = threadIdx.x;
    const int r0 = blockIdx.x * 32;
    float s = 0.f, sq = 0.f;
#pragma unroll 8
    for (int r = 0; r < 32; r++) {
        float v = z[(r0 + r) * K + k];
        s += v; sq += v * v;
    }
    g_pS[blockIdx.x * K + k] = s;
    g_pQ[blockIdx.x * K + k] = sq;
}

// ---------------------------------------------------------------------------
// S2: finalize mean/rstd; zero g_T and g_S.
// ---------------------------------------------------------------------------
__global__ __launch_bounds__(128) void finalize_kernel() {
    const int k = threadIdx.x;
    float s = 0.f, sq = 0.f;
#pragma unroll 8
    for (int b = 0; b < 64; b++) {
        s  += g_pS[b * K + k];
        sq += g_pQ[b * K + k];
    }
    float mean = s / (float)N;
    float var = (sq - s * mean) / (float)(N - 1);
    var = fmaxf(var, 0.f);
    g_mean[k] = mean;
    g_rs[k] = 1.f / (sqrtf(var) + 1e-6f);
#pragma unroll
    for (int r = 0; r < NMAX; r++) g_T[r * K + k] = 0.f;
#pragma unroll
    for (int r = 0; r < N / K; r++) g_S[r * K + k] = 0.f;
}

// ---------------------------------------------------------------------------
// S3: standardize + moments. 256 blocks x 8 rows; thread = column k.
// 4 independent recurrence chains (ILP). 1/(n+1) folded as immediates.
// ---------------------------------------------------------------------------
__global__ __launch_bounds__(128) void standmom_kernel(const float* __restrict__ z) {
    const int k = threadIdx.x;
    const int r0 = blockIdx.x * 8;
    const float mean = g_mean[k], rs = g_rs[k];

    float acc[NMAX];
#pragma unroll
    for (int n = 0; n < NMAX; n++) acc[n] = 0.f;

#pragma unroll
    for (int g = 0; g < 2; g++) {
        float b[4], q[4];
#pragma unroll
        for (int r = 0; r < 4; r++) {
            int row = r0 + g * 4 + r;
            float v = z[row * K + k];
            float xs = (v - mean) * rs;
            g_xs[row * K + k] = xs;
            g_u [row * K + k] = xs * SQL2E;
            b[r] = xs;
            q[r] = ex2f(NL2E * xs * xs);
        }
#pragma unroll
        for (int n = 0; n < NMAX; n++) {
            const float rinv = 1.0f / (float)(n + 1);
#pragma unroll
            for (int r = 0; r < 4; r++) {
                acc[n] += q[r];
                q[r] *= b[r] * rinv;
            }
        }
    }
#pragma unroll
    for (int n = 0; n < NMAX; n++) atomicAdd(&g_T[n * K + k], acc[n]);
}

// ---------------------------------------------------------------------------
// R: per-row 0.5*||u_i||^2.
// ---------------------------------------------------------------------------
__global__ __launch_bounds__(256) void rownorm_kernel() {
    const int warp = threadIdx.x >> 5, lane = threadIdx.x & 31;
    const int i = blockIdx.x * 8 + warp;
    const float4 v = reinterpret_cast<const float4*>(g_u)[i * 32 + lane];
    float h = v.x * v.x + v.y * v.y + v.z * v.z + v.w * v.w;
#pragma unroll
    for (int o = 16; o; o >>= 1) h += __shfl_xor_sync(0xffffffffu, h, o);
    if (lane == 0) g_rh[i] = 0.5f * h;
}

// ---------------------------------------------------------------------------
// G: symmetric Gram (fma.rn.f32x2 packed) + fused exp + row/col sums.
// ---------------------------------------------------------------------------
__global__ __launch_bounds__(256) void gram_kernel() {
    __shared__ float As[32][132];
    __shared__ float Bs[32][132];
    __shared__ float colP[16][128];

    const int tid = threadIdx.x;
    const int tx = tid & 15, ty = tid >> 4;

    int rem = blockIdx.x, ti = 0;
    for (int t = 0; t < 16; t++) {
        int L = 16 - t;
        if (rem < L) { ti = t; break; }
        rem -= L;
    }
    const int tj = ti + rem;
    const int i0 = ti * 128, j0 = tj * 128;

    ull acc2[8][4];
#pragma unroll
    for (int m = 0; m < 8; m++)
#pragma unroll
        for (int p = 0; p < 4; p++) acc2[m][p] = splat2(0.f);

#pragma unroll 1
    for (int kc = 0; kc < K; kc += 32) {
        __syncthreads();
#pragma unroll
        for (int r = 0; r < 4; r++) {
            int f = tid + 256 * r;
            int row = f >> 3, kp = (f & 7) * 4;
            float4 va = *(const float4*)&g_u[(i0 + row) * K + kc + kp];
            As[kp + 0][row] = va.x; As[kp + 1][row] = va.y;
            As[kp + 2][row] = va.z; As[kp + 3][row] = va.w;
            float4 vb = *(const float4*)&g_u[(j0 + row) * K + kc + kp];
            Bs[kp + 0][row] = vb.x; Bs[kp + 1][row] = vb.y;
            Bs[kp + 2][row] = vb.z; Bs[kp + 3][row] = vb.w;
        }
        __syncthreads();
#pragma unroll
        for (int kk = 0; kk < 32; kk++) {
            float4 a0 = *(const float4*)&As[kk][ty * 8];
            float4 a1 = *(const float4*)&As[kk][ty * 8 + 4];
            float4 b0 = *(const float4*)&Bs[kk][tx * 8];
            float4 b1 = *(const float4*)&Bs[kk][tx * 8 + 4];
            ull av2[8];
            av2[0] = splat2(a0.x); av2[1] = splat2(a0.y);
            av2[2] = splat2(a0.z); av2[3] = splat2(a0.w);
            av2[4] = splat2(a1.x); av2[5] = splat2(a1.y);
            av2[6] = splat2(a1.z); av2[7] = splat2(a1.w);
            ull bv[4];
            bv[0] = pack2(b0.x, b0.y); bv[1] = pack2(b0.z, b0.w);
            bv[2] = pack2(b1.x, b1.y); bv[3] = pack2(b1.z, b1.w);
#pragma unroll
            for (int m = 0; m < 8; m++)
#pragma unroll
                for (int p = 0; p < 4; p++)
                    acc2[m][p] = fma2(av2[m], bv[p], acc2[m][p]);
        }
    }

    float rhi[8], rhj[8];
#pragma unroll
    for (int m = 0; m < 8; m++) rhi[m] = g_rh[i0 + ty * 8 + m];
#pragma unroll
    for (int n = 0; n < 8; n++) rhj[n] = g_rh[j0 + tx * 8 + n];

    float rows[8], cols[8];
#pragma unroll
    for (int m = 0; m < 8; m++) rows[m] = 0.f;
#pragma unroll
    for (int n = 0; n < 8; n++) cols[n] = 0.f;
#pragma unroll
    for (int m = 0; m < 8; m++) {
#pragma unroll
        for (int p = 0; p < 4; p++) {
            float glo, ghi;
            unpack2(acc2[m][p], glo, ghi);
            float e0 = ex2f(glo - rhi[m] - rhj[2 * p + 0]);
            float e1 = ex2f(ghi - rhi[m] - rhj[2 * p + 1]);
            rows[m] += e0 + e1;
            cols[2 * p + 0] += e0;
            cols[2 * p + 1] += e1;
        }
    }

#pragma unroll
    for (int o = 8; o; o >>= 1)
#pragma unroll
        for (int m = 0; m < 8; m++)
            rows[m] += __shfl_xor_sync(0xffffffffu, rows[m], o);
    if (tx == 0) {
#pragma unroll
        for (int m = 0; m < 8; m++)
            atomicAdd(&g_S[i0 + ty * 8 + m], rows[m]);
    }

#pragma unroll
    for (int n = 0; n < 8; n++) colP[ty][tx * 8 + n] = cols[n];
    __syncthreads();
    if (ti != tj && tid < 128) {
        float s = 0.f;
#pragma unroll
        for (int t = 0; t < 16; t++) s += colP[t][tid];
        atomicAdd(&g_S[j0 + tid], s);
    }
}

// ---------------------------------------------------------------------------
// C: combine. Block = 8 rows, thread = column k. T staged in smem; __logf.
// ---------------------------------------------------------------------------
__global__ __launch_bounds__(128) void combine_kernel() {
    __shared__ float T_sh[NMAX * K];   // 32 KB
    const int k = threadIdx.x;
    const int i0 = blockIdx.x * 8;

    // cooperative coalesced load of T
#pragma unroll
    for (int r = 0; r < 16; r++)
        reinterpret_cast<float4*>(T_sh)[k + 128 * r] =
            reinterpret_cast<const float4*>(g_T)[k + 128 * r];
    __syncthreads();

    float a[8], S[8];
#pragma unroll
    for (int r = 0; r < 8; r++) a[r] = g_xs[(i0 + r) * K + k];
    {
        float t = T_sh[(NMAX - 1) * K + k];
#pragma unroll
        for (int r = 0; r < 8; r++) S[r] = t;
    }
#pragma unroll
    for (int n = NMAX - 2; n >= 0; n--) {
        float t = T_sh[n * K + k];
#pragma unroll
        for (int r = 0; r < 8; r++) S[r] = fmaf(S[r], a[r], t);
    }

    float val[8];
#pragma unroll
    for (int r = 0; r < 8; r++)
        val[r] = lnf(S[r]) - 0.5f * a[r] * a[r];

#pragma unroll
    for (int o = 16; o; o >>= 1)
#pragma unroll
        for (int r = 0; r < 8; r++)
            val[r] += __shfl_xor_sync(0xffffffffu, val[r], o);

    __shared__ float part[4][8];
    const int w = k >> 5, lane = k & 31;
    if (lane == 0) {
#pragma unroll
        for (int r = 0; r < 8; r++) part[w][r] = val[r];
    }
    __syncthreads();
    if (k < 8) {
        float tot = part[0][k] + part[1][k] + part[2][k] + part[3][k];
        g_v[i0 + k] = logf(g_S[i0 + k]) - tot;
    }
}

// ---------------------------------------------------------------------------
// F: mean + (K-1)*ln N
// ---------------------------------------------------------------------------
__global__ __launch_bounds__(256) void finish_kernel(float* __restrict__ out) {
    __shared__ float sh[256];
    const int t = threadIdx.x;
    float s = 0.f;
    for (int r = t; r < N; r += 256) s += g_v[r];
    sh[t] = s;
    __syncthreads();
    for (int off = 128; off > 0; off >>= 1) {
        if (t < off) sh[t] += sh[t + off];
        __syncthreads();
    }
    if (t == 0)
        out[0] = sh[0] / (float)N + (float)(K - 1) * logf((float)N);
}

// ---------------------------------------------------------------------------
extern "C" void kernel_launch(void* const* d_in, const int* in_sizes, int n_in,
                              void* d_out, int out_size) {
    (void)in_sizes; (void)n_in; (void)out_size;
    const float* z = (const float*)d_in[0];
    float* out = (float*)d_out;

    sums_kernel    <<<64, 128>>>(z);
    finalize_kernel<<<1, 128>>>();
    standmom_kernel<<<256, 128>>>(z);
    rownorm_kernel <<<N / 8, 256>>>();
    gram_kernel    <<<136, 256>>>();
    combine_kernel <<<N / 8, 128>>>();
    finish_kernel  <<<1, 256>>>(out);
}

// round 6
// speedup vs baseline: 6.8716x; 1.1556x over previous
#include <cuda_runtime.h>
#include <math.h>

#define N    2048
#define K    128
#define NMAX 64

#define SQL2E 1.2011224087864498f   // sqrt(log2(e))
#define NL2E  -0.7213475204444817f  // -0.5*log2(e)
#define HL2E  0.7213475204444817f   // 0.5*log2(e)

typedef unsigned long long ull;

__device__ float g_u  [N * K];      // standardized * sqrt(log2 e)
__device__ float g_xs [N * K];      // standardized
__device__ float g_rh [N];          // 0.5*||u_i||^2
__device__ float g_S  [N];          // joint sums
__device__ float g_T  [NMAX * K];   // scaled moments
__device__ float g_pS [64 * K];     // partial column sums
__device__ float g_pQ [64 * K];     // partial column sumsq
__device__ float g_acc;             // final sum of v_i
__device__ unsigned g_cnt;          // combine-block arrival counter

__device__ __forceinline__ float ex2f(float x) {
    float r; asm("ex2.approx.f32 %0, %1;" : "=f"(r) : "f"(x)); return r;
}
__device__ __forceinline__ float lg2f(float x) {
    float r; asm("lg2.approx.f32 %0, %1;" : "=f"(r) : "f"(x)); return r;
}
#define LN2f 0.6931471805599453f
__device__ __forceinline__ float lnf(float x) { return lg2f(x) * LN2f; }

__device__ __forceinline__ ull splat2(float x) {
    ull r; asm("mov.b64 %0, {%1, %1};" : "=l"(r) : "f"(x)); return r;
}
__device__ __forceinline__ ull pack2(float lo, float hi) {
    ull r; asm("mov.b64 %0, {%1, %2};" : "=l"(r) : "f"(lo), "f"(hi)); return r;
}
__device__ __forceinline__ ull fma2(ull a, ull b, ull c) {
    ull d; asm("fma.rn.f32x2 %0, %1, %2, %3;" : "=l"(d) : "l"(a), "l"(b), "l"(c)); return d;
}
__device__ __forceinline__ void unpack2(ull v, float& lo, float& hi) {
    asm("mov.b64 {%0, %1}, %2;" : "=f"(lo), "=f"(hi) : "l"(v));
}

// ---------------------------------------------------------------------------
// K1: partial column sums (coalesced) + zero all accumulators for this call.
// 64 blocks x 128 threads.
// ---------------------------------------------------------------------------
__global__ __launch_bounds__(128) void sums_kernel(const float* __restrict__ z) {
    const int k = threadIdx.x;
    const int b = blockIdx.x;
    const int r0 = b * 32;
    float s = 0.f, sq = 0.f;
#pragma unroll 8
    for (int r = 0; r < 32; r++) {
        float v = z[(r0 + r) * K + k];
        s += v; sq += v * v;
    }
    g_pS[b * K + k] = s;
    g_pQ[b * K + k] = sq;

    g_T[b * 128 + k] = 0.f;                 // 64*128 == NMAX*K
    if (b < 16) g_S[b * 128 + k] = 0.f;     // 16*128 == N
    if (b == 0 && k == 0) { g_acc = 0.f; g_cnt = 0u; }
}

// ---------------------------------------------------------------------------
// K2: finalize (redundant per block) + standardize + moments + row norms.
// 256 blocks x 128 threads; block = 8 rows, thread = column k.
// ---------------------------------------------------------------------------
__global__ __launch_bounds__(128) void standmom_kernel(const float* __restrict__ z) {
    const int k = threadIdx.x;
    const int r0 = blockIdx.x * 8;

    // redundant finalize: mean/rstd for column k
    float s = 0.f, sq = 0.f;
#pragma unroll 8
    for (int b = 0; b < 64; b++) {
        s  += g_pS[b * K + k];
        sq += g_pQ[b * K + k];
    }
    const float mean = s / (float)N;
    float var = (sq - s * mean) / (float)(N - 1);
    var = fmaxf(var, 0.f);
    const float rs = 1.f / (sqrtf(var) + 1e-6f);

    // standardize 8 rows; seed moment chains; collect row-norm contributions
    float bx[8], q[8], rh8[8];
#pragma unroll
    for (int r = 0; r < 8; r++) {
        int row = r0 + r;
        float xs = (z[row * K + k] - mean) * rs;
        g_xs[row * K + k] = xs;
        g_u [row * K + k] = xs * SQL2E;
        bx[r] = xs;
        q[r]  = ex2f(NL2E * xs * xs);
        rh8[r] = xs * xs;
    }

    // scaled moments: acc[n] = sum_r q_r ; q <- q * b / (n+1)
    float acc[NMAX];
#pragma unroll
    for (int n = 0; n < NMAX; n++) acc[n] = 0.f;
#pragma unroll
    for (int n = 0; n < NMAX; n++) {
        const float rinv = 1.0f / (float)(n + 1);
#pragma unroll
        for (int r = 0; r < 8; r++) {
            acc[n] += q[r];
            q[r] *= bx[r] * rinv;
        }
    }
#pragma unroll
    for (int n = 0; n < NMAX; n++) atomicAdd(&g_T[n * K + k], acc[n]);

    // row norms: g_rh[i] = 0.5*log2(e)*sum_k xs^2
#pragma unroll
    for (int o = 16; o; o >>= 1)
#pragma unroll
        for (int r = 0; r < 8; r++)
            rh8[r] += __shfl_xor_sync(0xffffffffu, rh8[r], o);

    __shared__ float shr[4][8];
    const int w = k >> 5, lane = k & 31;
    if (lane == 0) {
#pragma unroll
        for (int r = 0; r < 8; r++) shr[w][r] = rh8[r];
    }
    __syncthreads();
    if (k < 8)
        g_rh[r0 + k] = HL2E * (shr[0][k] + shr[1][k] + shr[2][k] + shr[3][k]);
}

// ---------------------------------------------------------------------------
// K3: symmetric Gram (fma.rn.f32x2) + fused exp + row/col sums.
// ---------------------------------------------------------------------------
__global__ __launch_bounds__(256) void gram_kernel() {
    __shared__ float As[32][132];
    __shared__ float Bs[32][132];
    __shared__ float colP[16][128];

    const int tid = threadIdx.x;
    const int tx = tid & 15, ty = tid >> 4;

    int rem = blockIdx.x, ti = 0;
    for (int t = 0; t < 16; t++) {
        int L = 16 - t;
        if (rem < L) { ti = t; break; }
        rem -= L;
    }
    const int tj = ti + rem;
    const int i0 = ti * 128, j0 = tj * 128;

    ull acc2[8][4];
#pragma unroll
    for (int m = 0; m < 8; m++)
#pragma unroll
        for (int p = 0; p < 4; p++) acc2[m][p] = splat2(0.f);

#pragma unroll 1
    for (int kc = 0; kc < K; kc += 32) {
        __syncthreads();
#pragma unroll
        for (int r = 0; r < 4; r++) {
            int f = tid + 256 * r;
            int row = f >> 3, kp = (f & 7) * 4;
            float4 va = *(const float4*)&g_u[(i0 + row) * K + kc + kp];
            As[kp + 0][row] = va.x; As[kp + 1][row] = va.y;
            As[kp + 2][row] = va.z; As[kp + 3][row] = va.w;
            float4 vb = *(const float4*)&g_u[(j0 + row) * K + kc + kp];
            Bs[kp + 0][row] = vb.x; Bs[kp + 1][row] = vb.y;
            Bs[kp + 2][row] = vb.z; Bs[kp + 3][row] = vb.w;
        }
        __syncthreads();
#pragma unroll
        for (int kk = 0; kk < 32; kk++) {
            float4 a0 = *(const float4*)&As[kk][ty * 8];
            float4 a1 = *(const float4*)&As[kk][ty * 8 + 4];
            float4 b0 = *(const float4*)&Bs[kk][tx * 8];
            float4 b1 = *(const float4*)&Bs[kk][tx * 8 + 4];
            ull av2[8];
            av2[0] = splat2(a0.x); av2[1] = splat2(a0.y);
            av2[2] = splat2(a0.z); av2[3] = splat2(a0.w);
            av2[4] = splat2(a1.x); av2[5] = splat2(a1.y);
            av2[6] = splat2(a1.z); av2[7] = splat2(a1.w);
            ull bv[4];
            bv[0] = pack2(b0.x, b0.y); bv[1] = pack2(b0.z, b0.w);
            bv[2] = pack2(b1.x, b1.y); bv[3] = pack2(b1.z, b1.w);
#pragma unroll
            for (int m = 0; m < 8; m++)
#pragma unroll
                for (int p = 0; p < 4; p++)
                    acc2[m][p] = fma2(av2[m], bv[p], acc2[m][p]);
        }
    }

    float rhi[8], rhj[8];
#pragma unroll
    for (int m = 0; m < 8; m++) rhi[m] = g_rh[i0 + ty * 8 + m];
#pragma unroll
    for (int n = 0; n < 8; n++) rhj[n] = g_rh[j0 + tx * 8 + n];

    float rows[8], cols[8];
#pragma unroll
    for (int m = 0; m < 8; m++) rows[m] = 0.f;
#pragma unroll
    for (int n = 0; n < 8; n++) cols[n] = 0.f;
#pragma unroll
    for (int m = 0; m < 8; m++) {
#pragma unroll
        for (int p = 0; p < 4; p++) {
            float glo, ghi;
            unpack2(acc2[m][p], glo, ghi);
            float e0 = ex2f(glo - rhi[m] - rhj[2 * p + 0]);
            float e1 = ex2f(ghi - rhi[m] - rhj[2 * p + 1]);
            rows[m] += e0 + e1;
            cols[2 * p + 0] += e0;
            cols[2 * p + 1] += e1;
        }
    }

#pragma unroll
    for (int o = 8; o; o >>= 1)
#pragma unroll
        for (int m = 0; m < 8; m++)
            rows[m] += __shfl_xor_sync(0xffffffffu, rows[m], o);
    if (tx == 0) {
#pragma unroll
        for (int m = 0; m < 8; m++)
            atomicAdd(&g_S[i0 + ty * 8 + m], rows[m]);
    }

#pragma unroll
    for (int n = 0; n < 8; n++) colP[ty][tx * 8 + n] = cols[n];
    __syncthreads();
    if (ti != tj && tid < 128) {
        float ssum = 0.f;
#pragma unroll
        for (int t = 0; t < 16; t++) ssum += colP[t][tid];
        atomicAdd(&g_S[j0 + tid], ssum);
    }
}

// ---------------------------------------------------------------------------
// K4: combine + finish. Block = 8 rows, thread = column k.
// Horner over smem-staged T; per-block sum atomically accumulated; last
// block writes the scalar output.
// ---------------------------------------------------------------------------
__global__ __launch_bounds__(128) void combine_kernel(float* __restrict__ out) {
    __shared__ float T_sh[NMAX * K];   // 32 KB
    const int k = threadIdx.x;
    const int i0 = blockIdx.x * 8;

#pragma unroll
    for (int r = 0; r < 16; r++)
        reinterpret_cast<float4*>(T_sh)[k + 128 * r] =
            reinterpret_cast<const float4*>(g_T)[k + 128 * r];
    __syncthreads();

    float a[8], S[8];
#pragma unroll
    for (int r = 0; r < 8; r++) a[r] = g_xs[(i0 + r) * K + k];
    {
        float t = T_sh[(NMAX - 1) * K + k];
#pragma unroll
        for (int r = 0; r < 8; r++) S[r] = t;
    }
#pragma unroll
    for (int n = NMAX - 2; n >= 0; n--) {
        float t = T_sh[n * K + k];
#pragma unroll
        for (int r = 0; r < 8; r++) S[r] = fmaf(S[r], a[r], t);
    }

    float val[8];
#pragma unroll
    for (int r = 0; r < 8; r++)
        val[r] = lnf(S[r]) - 0.5f * a[r] * a[r];

#pragma unroll
    for (int o = 16; o; o >>= 1)
#pragma unroll
        for (int r = 0; r < 8; r++)
            val[r] += __shfl_xor_sync(0xffffffffu, val[r], o);

    __shared__ float part[4][8];
    __shared__ float vrow[8];
    const int w = k >> 5, lane = k & 31;
    if (lane == 0) {
#pragma unroll
        for (int r = 0; r < 8; r++) part[w][r] = val[r];
    }
    __syncthreads();
    if (k < 8) {
        float tot = part[0][k] + part[1][k] + part[2][k] + part[3][k];
        vrow[k] = logf(g_S[i0 + k]) - tot;     // v_i
    }
    __syncthreads();

    if (k == 0) {
        float bsum = 0.f;
#pragma unroll
        for (int r = 0; r < 8; r++) bsum += vrow[r];
        atomicAdd(&g_acc, bsum);
        __threadfence();
        unsigned old = atomicAdd(&g_cnt, 1u);
        if (old == (unsigned)(gridDim.x - 1)) {
            __threadfence();
            out[0] = g_acc / (float)N + (float)(K - 1) * logf((float)N);
        }
    }
}

// ---------------------------------------------------------------------------
extern "C" void kernel_launch(void* const* d_in, const int* in_sizes, int n_in,
                              void* d_out, int out_size) {
    (void)in_sizes; (void)n_in; (void)out_size;
    const float* z = (const float*)d_in[0];
    float* out = (float*)d_out;

    sums_kernel    <<<64, 128>>>(z);
    standmom_kernel<<<256, 128>>>(z);
    gram_kernel    <<<136, 256>>>();
    combine_kernel <<<256, 128>>>(out);
}

// round 7
// speedup vs baseline: 7.3131x; 1.0643x over previous
#include <cuda_runtime.h>
#include <math.h>

#define N    2048
#define K    128
#define NMAX 48

#define SQL2E 1.2011224087864498f   // sqrt(log2(e))
#define NL2E  -0.7213475204444817f  // -0.5*log2(e)
#define HL2E  0.7213475204444817f   // 0.5*log2(e)

typedef unsigned long long ull;

__device__ float g_u  [N * K];      // standardized * sqrt(log2 e)
__device__ float g_xs [N * K];      // standardized
__device__ float g_rh [N];          // 0.5*log2(e)*||xs_i||^2
__device__ float g_S  [N];          // joint sums
__device__ float g_T  [NMAX * K];   // scaled moments
__device__ float g_pS [64 * K];     // partial column sums
__device__ float g_pQ [64 * K];     // partial column sumsq
__device__ float g_acc;             // final sum of v_i
__device__ unsigned g_cnt;          // combine-block arrival counter

__device__ __forceinline__ float ex2f(float x) {
    float r; asm("ex2.approx.f32 %0, %1;" : "=f"(r) : "f"(x)); return r;
}
__device__ __forceinline__ float lg2f(float x) {
    float r; asm("lg2.approx.f32 %0, %1;" : "=f"(r) : "f"(x)); return r;
}
#define LN2f 0.6931471805599453f
__device__ __forceinline__ float lnf(float x) { return lg2f(x) * LN2f; }

__device__ __forceinline__ ull splat2(float x) {
    ull r; asm("mov.b64 %0, {%1, %1};" : "=l"(r) : "f"(x)); return r;
}
__device__ __forceinline__ ull pack2(float lo, float hi) {
    ull r; asm("mov.b64 %0, {%1, %2};" : "=l"(r) : "f"(lo), "f"(hi)); return r;
}
__device__ __forceinline__ ull fma2(ull a, ull b, ull c) {
    ull d; asm("fma.rn.f32x2 %0, %1, %2, %3;" : "=l"(d) : "l"(a), "l"(b), "l"(c)); return d;
}
__device__ __forceinline__ void unpack2(ull v, float& lo, float& hi) {
    asm("mov.b64 {%0, %1}, %2;" : "=f"(lo), "=f"(hi) : "l"(v));
}

// ---------------------------------------------------------------------------
// K1: partial column sums (coalesced) + zero all accumulators for this call.
// 64 blocks x 128 threads.
// ---------------------------------------------------------------------------
__global__ __launch_bounds__(128) void sums_kernel(const float* __restrict__ z) {
    const int k = threadIdx.x;
    const int b = blockIdx.x;
    const int r0 = b * 32;
    float s = 0.f, sq = 0.f;
#pragma unroll 8
    for (int r = 0; r < 32; r++) {
        float v = z[(r0 + r) * K + k];
        s += v; sq += v * v;
    }
    g_pS[b * K + k] = s;
    g_pQ[b * K + k] = sq;

    if (b < NMAX) g_T[b * 128 + k] = 0.f;              // 48*128
    else          g_S[(b - NMAX) * 128 + k] = 0.f;     // 16*128 == N
    if (b == 0 && k == 0) { g_acc = 0.f; g_cnt = 0u; }
}

// ---------------------------------------------------------------------------
// K2: finalize (redundant per block) + standardize + moments + row norms.
// 128 blocks x 128 threads; block = 16 rows, thread = column k.
// ---------------------------------------------------------------------------
__global__ __launch_bounds__(128) void standmom_kernel(const float* __restrict__ z) {
    const int k = threadIdx.x;
    const int r0 = blockIdx.x * 16;

    // redundant finalize: mean/rstd for column k
    float s = 0.f, sq = 0.f;
#pragma unroll 8
    for (int b = 0; b < 64; b++) {
        s  += g_pS[b * K + k];
        sq += g_pQ[b * K + k];
    }
    const float mean = s / (float)N;
    float var = (sq - s * mean) / (float)(N - 1);
    var = fmaxf(var, 0.f);
    const float rs = 1.f / (sqrtf(var) + 1e-6f);

    // standardize 16 rows; seed moment chains; row-norm contributions
    float bx[16], q[16], rh16[16];
#pragma unroll
    for (int r = 0; r < 16; r++) {
        int row = r0 + r;
        float xs = (z[row * K + k] - mean) * rs;
        g_xs[row * K + k] = xs;
        g_u [row * K + k] = xs * SQL2E;
        bx[r] = xs;
        q[r]  = ex2f(NL2E * xs * xs);
        rh16[r] = xs * xs;
    }

    // scaled moments: acc[n] = sum_r q_r ; q <- q * b / (n+1)
    float acc[NMAX];
#pragma unroll
    for (int n = 0; n < NMAX; n++) acc[n] = 0.f;
#pragma unroll
    for (int n = 0; n < NMAX; n++) {
        const float rinv = 1.0f / (float)(n + 1);
#pragma unroll
        for (int r = 0; r < 16; r++) {
            acc[n] += q[r];
            q[r] *= bx[r] * rinv;
        }
    }
#pragma unroll
    for (int n = 0; n < NMAX; n++) atomicAdd(&g_T[n * K + k], acc[n]);

    // row norms: g_rh[i] = 0.5*log2(e)*sum_k xs^2
#pragma unroll
    for (int o = 16; o; o >>= 1)
#pragma unroll
        for (int r = 0; r < 16; r++)
            rh16[r] += __shfl_xor_sync(0xffffffffu, rh16[r], o);

    __shared__ float shr[4][16];
    const int w = k >> 5, lane = k & 31;
    if (lane == 0) {
#pragma unroll
        for (int r = 0; r < 16; r++) shr[w][r] = rh16[r];
    }
    __syncthreads();
    if (k < 16)
        g_rh[r0 + k] = HL2E * (shr[0][k] + shr[1][k] + shr[2][k] + shr[3][k]);
}

// ---------------------------------------------------------------------------
// K3: symmetric Gram (fma.rn.f32x2) + fused exp + row/col sums.
// ---------------------------------------------------------------------------
__global__ __launch_bounds__(256) void gram_kernel() {
    __shared__ float As[32][132];
    __shared__ float Bs[32][132];
    __shared__ float colP[16][128];

    const int tid = threadIdx.x;
    const int tx = tid & 15, ty = tid >> 4;

    int rem = blockIdx.x, ti = 0;
    for (int t = 0; t < 16; t++) {
        int L = 16 - t;
        if (rem < L) { ti = t; break; }
        rem -= L;
    }
    const int tj = ti + rem;
    const int i0 = ti * 128, j0 = tj * 128;

    ull acc2[8][4];
#pragma unroll
    for (int m = 0; m < 8; m++)
#pragma unroll
        for (int p = 0; p < 4; p++) acc2[m][p] = splat2(0.f);

#pragma unroll 1
    for (int kc = 0; kc < K; kc += 32) {
        __syncthreads();
#pragma unroll
        for (int r = 0; r < 4; r++) {
            int f = tid + 256 * r;
            int row = f >> 3, kp = (f & 7) * 4;
            float4 va = *(const float4*)&g_u[(i0 + row) * K + kc + kp];
            As[kp + 0][row] = va.x; As[kp + 1][row] = va.y;
            As[kp + 2][row] = va.z; As[kp + 3][row] = va.w;
            float4 vb = *(const float4*)&g_u[(j0 + row) * K + kc + kp];
            Bs[kp + 0][row] = vb.x; Bs[kp + 1][row] = vb.y;
            Bs[kp + 2][row] = vb.z; Bs[kp + 3][row] = vb.w;
        }
        __syncthreads();
#pragma unroll
        for (int kk = 0; kk < 32; kk++) {
            float4 a0 = *(const float4*)&As[kk][ty * 8];
            float4 a1 = *(const float4*)&As[kk][ty * 8 + 4];
            float4 b0 = *(const float4*)&Bs[kk][tx * 8];
            float4 b1 = *(const float4*)&Bs[kk][tx * 8 + 4];
            ull av2[8];
            av2[0] = splat2(a0.x); av2[1] = splat2(a0.y);
            av2[2] = splat2(a0.z); av2[3] = splat2(a0.w);
            av2[4] = splat2(a1.x); av2[5] = splat2(a1.y);
            av2[6] = splat2(a1.z); av2[7] = splat2(a1.w);
            ull bv[4];
            bv[0] = pack2(b0.x, b0.y); bv[1] = pack2(b0.z, b0.w);
            bv[2] = pack2(b1.x, b1.y); bv[3] = pack2(b1.z, b1.w);
#pragma unroll
            for (int m = 0; m < 8; m++)
#pragma unroll
                for (int p = 0; p < 4; p++)
                    acc2[m][p] = fma2(av2[m], bv[p], acc2[m][p]);
        }
    }

    float rhi[8], rhj[8];
#pragma unroll
    for (int m = 0; m < 8; m++) rhi[m] = g_rh[i0 + ty * 8 + m];
#pragma unroll
    for (int n = 0; n < 8; n++) rhj[n] = g_rh[j0 + tx * 8 + n];

    float rows[8], cols[8];
#pragma unroll
    for (int m = 0; m < 8; m++) rows[m] = 0.f;
#pragma unroll
    for (int n = 0; n < 8; n++) cols[n] = 0.f;
#pragma unroll
    for (int m = 0; m < 8; m++) {
#pragma unroll
        for (int p = 0; p < 4; p++) {
            float glo, ghi;
            unpack2(acc2[m][p], glo, ghi);
            float e0 = ex2f(glo - rhi[m] - rhj[2 * p + 0]);
            float e1 = ex2f(ghi - rhi[m] - rhj[2 * p + 1]);
            rows[m] += e0 + e1;
            cols[2 * p + 0] += e0;
            cols[2 * p + 1] += e1;
        }
    }

#pragma unroll
    for (int o = 8; o; o >>= 1)
#pragma unroll
        for (int m = 0; m < 8; m++)
            rows[m] += __shfl_xor_sync(0xffffffffu, rows[m], o);
    if (tx == 0) {
#pragma unroll
        for (int m = 0; m < 8; m++)
            atomicAdd(&g_S[i0 + ty * 8 + m], rows[m]);
    }

#pragma unroll
    for (int n = 0; n < 8; n++) colP[ty][tx * 8 + n] = cols[n];
    __syncthreads();
    if (ti != tj && tid < 128) {
        float ssum = 0.f;
#pragma unroll
        for (int t = 0; t < 16; t++) ssum += colP[t][tid];
        atomicAdd(&g_S[j0 + tid], ssum);
    }
}

// ---------------------------------------------------------------------------
// K4: combine + finish. 64 blocks x 512 threads; block = 32 rows.
// Thread: k = tid&127, row-group g = tid>>7 (8 rows each).
// ---------------------------------------------------------------------------
__global__ __launch_bounds__(512) void combine_kernel(float* __restrict__ out) {
    __shared__ float T_sh[NMAX * K];   // 24 KB
    const int tid = threadIdx.x;
    const int k = tid & 127;
    const int g = tid >> 7;
    const int i0 = blockIdx.x * 32;
    const int r0 = i0 + g * 8;

    // cooperative coalesced load of T (1536 float4 / 512 threads = 3 each)
#pragma unroll
    for (int r = 0; r < 3; r++)
        reinterpret_cast<float4*>(T_sh)[tid + 512 * r] =
            reinterpret_cast<const float4*>(g_T)[tid + 512 * r];
    __syncthreads();

    float a[8], S[8];
#pragma unroll
    for (int r = 0; r < 8; r++) a[r] = g_xs[(r0 + r) * K + k];
    {
        float t = T_sh[(NMAX - 1) * K + k];
#pragma unroll
        for (int r = 0; r < 8; r++) S[r] = t;
    }
#pragma unroll
    for (int n = NMAX - 2; n >= 0; n--) {
        float t = T_sh[n * K + k];
#pragma unroll
        for (int r = 0; r < 8; r++) S[r] = fmaf(S[r], a[r], t);
    }

    float val[8];
#pragma unroll
    for (int r = 0; r < 8; r++)
        val[r] = lnf(S[r]) - 0.5f * a[r] * a[r];

#pragma unroll
    for (int o = 16; o; o >>= 1)
#pragma unroll
        for (int r = 0; r < 8; r++)
            val[r] += __shfl_xor_sync(0xffffffffu, val[r], o);

    __shared__ float part[16][8];      // per warp, per row
    __shared__ float vv[32];
    const int ww = tid >> 5, lane = tid & 31;
    if (lane == 0) {
#pragma unroll
        for (int r = 0; r < 8; r++) part[ww][r] = val[r];
    }
    __syncthreads();
    if (tid < 32) {
        int gg = tid >> 3, rr = tid & 7;
        float tot = part[gg * 4 + 0][rr] + part[gg * 4 + 1][rr]
                  + part[gg * 4 + 2][rr] + part[gg * 4 + 3][rr];
        vv[tid] = logf(g_S[i0 + gg * 8 + rr]) - tot;   // v_i
    }
    __syncthreads();

    if (tid == 0) {
        float bsum = 0.f;
#pragma unroll
        for (int r = 0; r < 32; r++) bsum += vv[r];
        atomicAdd(&g_acc, bsum);
        __threadfence();
        unsigned old = atomicAdd(&g_cnt, 1u);
        if (old == (unsigned)(gridDim.x - 1)) {
            __threadfence();
            out[0] = g_acc / (float)N + (float)(K - 1) * logf((float)N);
        }
    }
}

// ---------------------------------------------------------------------------
extern "C" void kernel_launch(void* const* d_in, const int* in_sizes, int n_in,
                              void* d_out, int out_size) {
    (void)in_sizes; (void)n_in; (void)out_size;
    const float* z = (const float*)d_in[0];
    float* out = (float*)d_out;

    sums_kernel    <<<64, 128>>>(z);
    standmom_kernel<<<128, 128>>>(z);
    gram_kernel    <<<136, 256>>>();
    combine_kernel <<<64, 512>>>(out);
}